// round 1
// baseline (speedup 1.0000x reference)
#include <cuda_runtime.h>
#include <math_constants.h>

#define BSZ   2
#define SEQ   2048
#define HID   1024
#define NH    16
#define HD    64

// Scratch for projected Q/K/V, laid out [b*NH+h][s][d]  (16 MB each)
__device__ float g_q[BSZ * NH * SEQ * HD];
__device__ float g_k[BSZ * NH * SEQ * HD];
__device__ float g_v[BSZ * NH * SEQ * HD];

// ---------------------------------------------------------------------------
// QKV projection: out[m][n] = sum_k X[m][k] * W[n][k] + bias[n]
// M = B*S = 4096, N = 1024, K = 1024.  64x64 tile, 256 threads, 4x4/thread.
// blockIdx.z selects (Wq,bq)->g_q, (Wk,bk)->g_k, (Wv,bv)->g_v.
// Output written directly in [b,h,s,d] layout.
// ---------------------------------------------------------------------------
__global__ __launch_bounds__(256) void qkv_kernel(
    const float* __restrict__ X,
    const float* __restrict__ Wq, const float* __restrict__ bq,
    const float* __restrict__ Wk, const float* __restrict__ bk,
    const float* __restrict__ Wv, const float* __restrict__ bv)
{
    const float* W; const float* bias; float* out;
    if (blockIdx.z == 0)      { W = Wq; bias = bq; out = g_q; }
    else if (blockIdx.z == 1) { W = Wk; bias = bk; out = g_k; }
    else                      { W = Wv; bias = bv; out = g_v; }

    // k-major tiles. Xs pitch 66 -> conflict-free transpose stores (scalar reads
    // are ty-broadcast). Ws pitch 68 -> 16B-aligned float4 reads.
    __shared__ float Xs[16 * 66];
    __shared__ float Ws[16 * 68];

    const int tid = threadIdx.x;
    const int tx  = tid & 15;
    const int ty  = tid >> 4;
    const int m0  = blockIdx.x * 64;
    const int n0  = blockIdx.y * 64;

    const int lr  = tid >> 2;        // tile row 0..63
    const int lc4 = (tid & 3) * 4;   // k offset within 16-wide k tile

    float acc[4][4] = {};

    for (int k0 = 0; k0 < HID; k0 += 16) {
        float4 xv = *(const float4*)&X[(m0 + lr) * HID + k0 + lc4];
        float4 wv = *(const float4*)&W[(n0 + lr) * HID + k0 + lc4];
        Xs[(lc4 + 0) * 66 + lr] = xv.x;
        Xs[(lc4 + 1) * 66 + lr] = xv.y;
        Xs[(lc4 + 2) * 66 + lr] = xv.z;
        Xs[(lc4 + 3) * 66 + lr] = xv.w;
        Ws[(lc4 + 0) * 68 + lr] = wv.x;
        Ws[(lc4 + 1) * 68 + lr] = wv.y;
        Ws[(lc4 + 2) * 68 + lr] = wv.z;
        Ws[(lc4 + 3) * 68 + lr] = wv.w;
        __syncthreads();

        #pragma unroll
        for (int k = 0; k < 16; k++) {
            float4 bN = *(const float4*)&Ws[k * 68 + tx * 4];
            float a0 = Xs[k * 66 + ty * 4 + 0];
            float a1 = Xs[k * 66 + ty * 4 + 1];
            float a2 = Xs[k * 66 + ty * 4 + 2];
            float a3 = Xs[k * 66 + ty * 4 + 3];
            acc[0][0] += a0 * bN.x; acc[0][1] += a0 * bN.y; acc[0][2] += a0 * bN.z; acc[0][3] += a0 * bN.w;
            acc[1][0] += a1 * bN.x; acc[1][1] += a1 * bN.y; acc[1][2] += a1 * bN.z; acc[1][3] += a1 * bN.w;
            acc[2][0] += a2 * bN.x; acc[2][1] += a2 * bN.y; acc[2][2] += a2 * bN.z; acc[2][3] += a2 * bN.w;
            acc[3][0] += a3 * bN.x; acc[3][1] += a3 * bN.y; acc[3][2] += a3 * bN.z; acc[3][3] += a3 * bN.w;
        }
        __syncthreads();
    }

    // Epilogue: n0 is a multiple of 64 => head h fixed per block, d = tx*4+j.
    float4 bb = *(const float4*)&bias[n0 + tx * 4];
    const int h = n0 >> 6;
    const int d = tx * 4;
    #pragma unroll
    for (int i = 0; i < 4; i++) {
        int m = m0 + ty * 4 + i;
        int b = m >> 11;            // m / SEQ
        int s = m & (SEQ - 1);
        float4 r = make_float4(acc[i][0] + bb.x, acc[i][1] + bb.y,
                               acc[i][2] + bb.z, acc[i][3] + bb.w);
        *(float4*)&out[((b * NH + h) * SEQ + s) * HD + d] = r;
    }
}

// ---------------------------------------------------------------------------
// Flash attention: one block = 64 queries of one (b,h). Online softmax over
// 32 key tiles of 64. 256 threads, 4x4 scores / 4x4 output per thread.
// ---------------------------------------------------------------------------
__global__ __launch_bounds__(256) void attn_kernel(
    const int* __restrict__ mask, float* __restrict__ out)
{
    extern __shared__ float sm[];
    float* Qs = sm;                    // [64 q ][68 d ]  float4 ld/st
    float* Ks = Qs + 64 * 68;          // [64 kv][67 d ]  scalar, ~2-way worst
    float* Vs = Ks + 64 * 67;          // [64 kv][68 d ]  float4 ld/st
    float* Ps = Vs + 64 * 68;          // [64 q ][68 kv]  float4 st, bcast ld
    int*   maskS = (int*)(Ps + 64 * 68);

    const int tid = threadIdx.x;
    const int tx  = tid & 15;
    const int ty  = tid >> 4;
    const int s0  = blockIdx.x * 64;
    const int bh  = blockIdx.y;
    const int b   = bh >> 4;

    const float* Qg = g_q + (bh * SEQ + s0) * HD;
    #pragma unroll
    for (int it = 0; it < 4; it++) {
        int idx = tid + it * 256;
        int row = idx >> 4;
        int c   = (idx & 15) * 4;
        *(float4*)&Qs[row * 68 + c] = *(const float4*)&Qg[row * HD + c];
    }

    float m_i[4], l_i[4], o[4][4];
    #pragma unroll
    for (int i = 0; i < 4; i++) {
        m_i[i] = -CUDART_INF_F; l_i[i] = 0.f;
        o[i][0] = o[i][1] = o[i][2] = o[i][3] = 0.f;
    }

    for (int kt = 0; kt < SEQ; kt += 64) {
        const float* Kg = g_k + (bh * SEQ + kt) * HD;
        const float* Vg = g_v + (bh * SEQ + kt) * HD;
        #pragma unroll
        for (int it = 0; it < 4; it++) {
            int idx = tid + it * 256;
            int row = idx >> 4;
            int c   = (idx & 15) * 4;
            float4 kv = *(const float4*)&Kg[row * HD + c];
            Ks[row * 67 + c + 0] = kv.x;
            Ks[row * 67 + c + 1] = kv.y;
            Ks[row * 67 + c + 2] = kv.z;
            Ks[row * 67 + c + 3] = kv.w;
            *(float4*)&Vs[row * 68 + c] = *(const float4*)&Vg[row * HD + c];
        }
        if (tid < 64) maskS[tid] = mask[b * SEQ + kt + tid];
        __syncthreads();

        // scores = Q · K^T  (64x64x64)
        float sc[4][4] = {};
        #pragma unroll 16
        for (int k = 0; k < 64; k++) {
            float a0 = Qs[(ty * 4 + 0) * 68 + k];
            float a1 = Qs[(ty * 4 + 1) * 68 + k];
            float a2 = Qs[(ty * 4 + 2) * 68 + k];
            float a3 = Qs[(ty * 4 + 3) * 68 + k];
            float b0 = Ks[(tx * 4 + 0) * 67 + k];
            float b1 = Ks[(tx * 4 + 1) * 67 + k];
            float b2 = Ks[(tx * 4 + 2) * 67 + k];
            float b3 = Ks[(tx * 4 + 3) * 67 + k];
            sc[0][0] += a0 * b0; sc[0][1] += a0 * b1; sc[0][2] += a0 * b2; sc[0][3] += a0 * b3;
            sc[1][0] += a1 * b0; sc[1][1] += a1 * b1; sc[1][2] += a1 * b2; sc[1][3] += a1 * b3;
            sc[2][0] += a2 * b0; sc[2][1] += a2 * b1; sc[2][2] += a2 * b2; sc[2][3] += a2 * b3;
            sc[3][0] += a3 * b0; sc[3][1] += a3 * b1; sc[3][2] += a3 * b2; sc[3][3] += a3 * b3;
        }

        // scale + mask (key positions with mask==0 -> -inf)
        #pragma unroll
        for (int j = 0; j < 4; j++) {
            bool ok = (maskS[tx * 4 + j] != 0);
            #pragma unroll
            for (int i = 0; i < 4; i++)
                sc[i][j] = ok ? sc[i][j] * 0.125f : -CUDART_INF_F;
        }

        // online softmax; 16 threads of a row are a contiguous 16-lane group
        #pragma unroll
        for (int i = 0; i < 4; i++) {
            float tm = fmaxf(fmaxf(sc[i][0], sc[i][1]), fmaxf(sc[i][2], sc[i][3]));
            #pragma unroll
            for (int off = 8; off; off >>= 1)
                tm = fmaxf(tm, __shfl_xor_sync(0xffffffffu, tm, off, 16));
            float m_new = fmaxf(m_i[i], tm);
            float mu = (m_new == -CUDART_INF_F) ? 0.f : m_new;
            float p0 = __expf(sc[i][0] - mu);
            float p1 = __expf(sc[i][1] - mu);
            float p2 = __expf(sc[i][2] - mu);
            float p3 = __expf(sc[i][3] - mu);
            float rs = (p0 + p1) + (p2 + p3);
            #pragma unroll
            for (int off = 8; off; off >>= 1)
                rs += __shfl_xor_sync(0xffffffffu, rs, off, 16);
            float alpha = __expf(m_i[i] - mu);
            l_i[i] = l_i[i] * alpha + rs;
            m_i[i] = m_new;
            o[i][0] *= alpha; o[i][1] *= alpha; o[i][2] *= alpha; o[i][3] *= alpha;
            *(float4*)&Ps[(ty * 4 + i) * 68 + tx * 4] = make_float4(p0, p1, p2, p3);
        }
        __syncthreads();

        // O += P · V   (64x64x64)
        #pragma unroll 16
        for (int k = 0; k < 64; k++) {
            float4 bV = *(const float4*)&Vs[k * 68 + tx * 4];
            float a0 = Ps[(ty * 4 + 0) * 68 + k];
            float a1 = Ps[(ty * 4 + 1) * 68 + k];
            float a2 = Ps[(ty * 4 + 2) * 68 + k];
            float a3 = Ps[(ty * 4 + 3) * 68 + k];
            o[0][0] += a0 * bV.x; o[0][1] += a0 * bV.y; o[0][2] += a0 * bV.z; o[0][3] += a0 * bV.w;
            o[1][0] += a1 * bV.x; o[1][1] += a1 * bV.y; o[1][2] += a1 * bV.z; o[1][3] += a1 * bV.w;
            o[2][0] += a2 * bV.x; o[2][1] += a2 * bV.y; o[2][2] += a2 * bV.z; o[2][3] += a2 * bV.w;
            o[3][0] += a3 * bV.x; o[3][1] += a3 * bV.y; o[3][2] += a3 * bV.z; o[3][3] += a3 * bV.w;
        }
        __syncthreads();
    }

    // epilogue: out[b][s][h*64 + d]
    const int h = bh & 15;
    #pragma unroll
    for (int i = 0; i < 4; i++) {
        float inv = 1.0f / fmaxf(l_i[i], 1e-30f);
        int s = s0 + ty * 4 + i;
        float4 r = make_float4(o[i][0] * inv, o[i][1] * inv,
                               o[i][2] * inv, o[i][3] * inv);
        *(float4*)&out[(b * SEQ + s) * HID + h * HD + tx * 4] = r;
    }
}

// ---------------------------------------------------------------------------
extern "C" void kernel_launch(void* const* d_in, const int* in_sizes, int n_in,
                              void* d_out, int out_size)
{
    const float* X    = (const float*)d_in[0];
    const int*   mask = (const int*)d_in[1];
    const float* Wq   = (const float*)d_in[2];
    const float* bq   = (const float*)d_in[3];
    const float* Wk   = (const float*)d_in[4];
    const float* bk   = (const float*)d_in[5];
    const float* Wv   = (const float*)d_in[6];
    const float* bv   = (const float*)d_in[7];
    float* out = (float*)d_out;

    qkv_kernel<<<dim3(64, 16, 3), 256>>>(X, Wq, bq, Wk, bk, Wv, bv);

    const int smem_bytes = (64 * 68 + 64 * 67 + 64 * 68 + 64 * 68) * 4 + 64 * 4;
    cudaFuncSetAttribute(attn_kernel,
                         cudaFuncAttributeMaxDynamicSharedMemorySize, smem_bytes);
    attn_kernel<<<dim3(SEQ / 64, BSZ * NH), 256, smem_bytes>>>(mask, out);
}

// round 3
// speedup vs baseline: 3.3397x; 3.3397x over previous
#include <cuda_runtime.h>
#include <math_constants.h>
#include <cstdint>

#define BSZ   2
#define SEQ   2048
#define HID   1024
#define NH    16
#define HD    64

// Scratch for projected Q/K/V, laid out [b*NH+h][s][d]
__device__ float g_q[BSZ * NH * SEQ * HD];
__device__ float g_k[BSZ * NH * SEQ * HD];
__device__ float g_v[BSZ * NH * SEQ * HD];

// ============================================================================
// helpers
// ============================================================================
__device__ __forceinline__ uint32_t smem_u32(const void* p) {
    uint32_t a;
    asm("{ .reg .u64 t; cvta.to.shared.u64 t, %1; cvt.u32.u64 %0, t; }"
        : "=r"(a) : "l"(p));
    return a;
}
__device__ __forceinline__ void cp16(uint32_t s, const void* g) {
    asm volatile("cp.async.cg.shared.global [%0], [%1], 16;" :: "r"(s), "l"(g));
}
__device__ __forceinline__ void cp_commit() {
    asm volatile("cp.async.commit_group;" ::: "memory");
}
__device__ __forceinline__ void cp_wait2() {
    asm volatile("cp.async.wait_group 2;" ::: "memory");
}
__device__ __forceinline__ uint32_t f2tf(float f) {
    uint32_t r;
    asm("cvt.rna.tf32.f32 %0, %1;" : "=r"(r) : "f"(f));
    return r;
}
__device__ __forceinline__ void ldm4(uint32_t* r, uint32_t addr) {
    asm volatile("ldmatrix.sync.aligned.m8n8.x4.shared.b16 {%0,%1,%2,%3}, [%4];"
                 : "=r"(r[0]), "=r"(r[1]), "=r"(r[2]), "=r"(r[3]) : "r"(addr));
}
__device__ __forceinline__ void mma_tf32(float* c, const uint32_t* a,
                                         uint32_t b0, uint32_t b1) {
    asm volatile(
        "mma.sync.aligned.m16n8k8.row.col.f32.tf32.tf32.f32 "
        "{%0,%1,%2,%3}, {%4,%5,%6,%7}, {%8,%9}, {%0,%1,%2,%3};"
        : "+f"(c[0]), "+f"(c[1]), "+f"(c[2]), "+f"(c[3])
        : "r"(a[0]), "r"(a[1]), "r"(a[2]), "r"(a[3]), "r"(b0), "r"(b1));
}

// ============================================================================
// QKV projection: out[m][n] = sum_k X[m][k]*W[n][k] + b[n]
// M=4096 N=1024 K=1024. CTA tile 128x128, BK=32, 3-stage cp.async, HMMA tf32.
// 256 threads = 8 warps (4 m x 2 n), warp tile 32x64.
// ============================================================================
#define QPITCH   36                       // floats per smem row (144B, 16B mult)
#define QA_BYTES (128 * QPITCH * 4)       // 18432
#define QSTAGE   (2 * QA_BYTES)           // 36864
#define QSTAGES  3
#define QKV_SMEM (QSTAGES * QSTAGE)       // 110592
#define QNKT     (HID / 32)               // 32

__global__ __launch_bounds__(256) void qkv_mma_kernel(
    const float* __restrict__ X,
    const float* __restrict__ Wq, const float* __restrict__ bq,
    const float* __restrict__ Wk, const float* __restrict__ bk,
    const float* __restrict__ Wv, const float* __restrict__ bv)
{
    const float* W; const float* bias; float* out;
    if (blockIdx.z == 0)      { W = Wq; bias = bq; out = g_q; }
    else if (blockIdx.z == 1) { W = Wk; bias = bk; out = g_k; }
    else                      { W = Wv; bias = bv; out = g_v; }

    extern __shared__ char smem[];
    const uint32_t sb = smem_u32(smem);

    const int tid  = threadIdx.x;
    const int wid  = tid >> 5;
    const int lane = tid & 31;
    const int wm   = wid >> 1;            // 0..3 -> m offset wm*32
    const int wn   = wid & 1;             // 0..1 -> n offset wn*64
    const int m0   = blockIdx.x * 128;
    const int n0   = blockIdx.y * 128;

    const float* gA0 = X + (size_t)m0 * HID;
    const float* gB0 = W + (size_t)n0 * HID;

    auto load_stage = [&](int stage, int kt) {
        const uint32_t sA = sb + stage * QSTAGE;
        const uint32_t sB = sA + QA_BYTES;
        const float* gA = gA0 + kt * 32;
        const float* gB = gB0 + kt * 32;
        #pragma unroll
        for (int i = 0; i < 4; i++) {
            int cid = tid + (i << 8);     // 0..1023
            int row = cid >> 3;           // 0..127
            int c   = cid & 7;            // 16B chunk within 128B row
            uint32_t off = row * (QPITCH * 4) + c * 16;
            cp16(sA + off, gA + row * HID + c * 4);
            cp16(sB + off, gB + row * HID + c * 4);
        }
    };

    load_stage(0, 0); cp_commit();
    load_stage(1, 1); cp_commit();
    load_stage(2, 2); cp_commit();

    float acc[2][8][4];
    #pragma unroll
    for (int mt = 0; mt < 2; mt++)
        #pragma unroll
        for (int nt = 0; nt < 8; nt++)
            acc[mt][nt][0] = acc[mt][nt][1] = acc[mt][nt][2] = acc[mt][nt][3] = 0.f;

    // ldmatrix lane address components
    const int a_row = (lane & 15);
    const int a_kof = (lane >> 4) * 4;
    const int b_row = (lane & 7) + ((lane >> 4) << 3);
    const int b_kof = ((lane >> 3) & 1) * 4;

    for (int kt = 0; kt < QNKT; kt++) {
        cp_wait2();
        __syncthreads();
        const uint32_t sA = sb + (kt % QSTAGES) * QSTAGE;
        const uint32_t sB = sA + QA_BYTES;

        #pragma unroll
        for (int k8 = 0; k8 < 4; k8++) {
            const int kc = k8 * 8;
            uint32_t af[2][4], bf[4][4];
            #pragma unroll
            for (int mt = 0; mt < 2; mt++)
                ldm4(af[mt], sA + ((wm * 32 + mt * 16 + a_row) * QPITCH + kc + a_kof) * 4);
            #pragma unroll
            for (int np = 0; np < 4; np++)
                ldm4(bf[np], sB + ((wn * 64 + np * 16 + b_row) * QPITCH + kc + b_kof) * 4);
            #pragma unroll
            for (int mt = 0; mt < 2; mt++)
                #pragma unroll
                for (int i = 0; i < 4; i++)
                    af[mt][i] = f2tf(__uint_as_float(af[mt][i]));
            #pragma unroll
            for (int np = 0; np < 4; np++)
                #pragma unroll
                for (int i = 0; i < 4; i++)
                    bf[np][i] = f2tf(__uint_as_float(bf[np][i]));
            #pragma unroll
            for (int mt = 0; mt < 2; mt++)
                #pragma unroll
                for (int nt = 0; nt < 8; nt++)
                    mma_tf32(acc[mt][nt], af[mt],
                             bf[nt >> 1][(nt & 1) * 2], bf[nt >> 1][(nt & 1) * 2 + 1]);
        }
        __syncthreads();
        if (kt + 3 < QNKT) load_stage(kt % QSTAGES, kt + 3);
        cp_commit();
    }

    // epilogue: warp covers rows m0+wm*32 .. +31, cols n0+wn*64 .. +63 (one head)
    const int n0g = n0 + wn * 64;
    const int h   = n0g >> 6;
    const int q2  = (lane & 3) * 2;
    #pragma unroll
    for (int mt = 0; mt < 2; mt++) {
        #pragma unroll
        for (int rh = 0; rh < 2; rh++) {
            int mrow = m0 + wm * 32 + mt * 16 + (lane >> 2) + rh * 8;
            int b = mrow >> 11;
            int s = mrow & (SEQ - 1);
            float* op = out + (((size_t)(b * NH + h) * SEQ + s) * HD);
            #pragma unroll
            for (int nt = 0; nt < 8; nt++) {
                int d = nt * 8 + q2;
                float2 bb = *(const float2*)&bias[n0g + d];
                float2 r = make_float2(acc[mt][nt][rh * 2 + 0] + bb.x,
                                       acc[mt][nt][rh * 2 + 1] + bb.y);
                *(float2*)&op[d] = r;
            }
        }
    }
}

// ============================================================================
// Flash attention with HMMA tf32. CTA = 64 queries of one (b,h). 4 warps,
// warp = 16 q rows. Q frags persist in regs; P round-trips via smem (aliased
// over the Q tile) for re-fragmenting; V stored transposed for the B operand.
// ============================================================================
#define APITCH 68                          // floats (272B, 16B mult, cf ldmatrix)
#define ATILE  (64 * APITCH)               // floats per tile
#define ATT_SMEM ((3 * ATILE + 64) * 4)    // QP + K + Vt + maskF

__global__ __launch_bounds__(128) void attn_mma_kernel(
    const int* __restrict__ mask, float* __restrict__ out)
{
    extern __shared__ float sm[];
    float* QPs   = sm;                     // Q tile, later P tile
    float* Ks    = sm + ATILE;
    float* Vt    = sm + 2 * ATILE;         // transposed V: [d][key]
    float* maskF = sm + 3 * ATILE;

    const uint32_t sQP = smem_u32(QPs);
    const uint32_t sK  = smem_u32(Ks);
    const uint32_t sV  = smem_u32(Vt);

    const int tid  = threadIdx.x;
    const int lane = tid & 31;
    const int w    = tid >> 5;             // warp 0..3 -> q rows 16w..16w+15
    const int s0   = blockIdx.x * 64;
    const int bh   = blockIdx.y;
    const int b    = bh >> 4;

    const int a_row = (lane & 15);
    const int a_kof = (lane >> 4) * 4;
    const int b_row = (lane & 7) + ((lane >> 4) << 3);
    const int b_kof = ((lane >> 3) & 1) * 4;
    const int q2    = (lane & 3) * 2;
    const int r0    = lane >> 2;

    // ---- load Q tile (tf32-converted) ----
    const float* Qg = g_q + (size_t)(bh * SEQ + s0) * HD;
    #pragma unroll
    for (int it = 0; it < 8; it++) {
        int cid = tid + it * 128;
        int row = cid >> 4;
        int c   = (cid & 15) * 4;
        float4 v = *(const float4*)&Qg[row * HD + c];
        uint4 u = make_uint4(f2tf(v.x), f2tf(v.y), f2tf(v.z), f2tf(v.w));
        *(uint4*)&QPs[row * APITCH + c] = u;
    }
    __syncthreads();

    // ---- Q fragments, persistent ----
    uint32_t aq[8][4];
    #pragma unroll
    for (int k8 = 0; k8 < 8; k8++)
        ldm4(aq[k8], sQP + ((16 * w + a_row) * APITCH + k8 * 8 + a_kof) * 4);

    float mI0 = -CUDART_INF_F, mI1 = -CUDART_INF_F, l0 = 0.f, l1 = 0.f;
    float o[8][4];
    #pragma unroll
    for (int dt = 0; dt < 8; dt++)
        o[dt][0] = o[dt][1] = o[dt][2] = o[dt][3] = 0.f;

    const int vd = tid & 63;               // d row handled by this thread
    const int vs0 = (tid >> 6) * 32;       // key half

    for (int kt = 0; kt < SEQ / 64; kt++) {
        __syncthreads();                   // prev iter consumers done (also Q frags)
        const float* Kg = g_k + (size_t)(bh * SEQ + kt * 64) * HD;
        const float* Vg = g_v + (size_t)(bh * SEQ + kt * 64) * HD;
        #pragma unroll
        for (int it = 0; it < 8; it++) {
            int cid = tid + it * 128;
            int row = cid >> 4;
            int c   = (cid & 15) * 4;
            float4 v = *(const float4*)&Kg[row * HD + c];
            uint4 u = make_uint4(f2tf(v.x), f2tf(v.y), f2tf(v.z), f2tf(v.w));
            *(uint4*)&Ks[row * APITCH + c] = u;
        }
        // V transposed: Vt[d][s]
        #pragma unroll
        for (int g = 0; g < 8; g++) {
            int s = vs0 + g * 4;
            uint4 u = make_uint4(f2tf(Vg[(s + 0) * HD + vd]),
                                 f2tf(Vg[(s + 1) * HD + vd]),
                                 f2tf(Vg[(s + 2) * HD + vd]),
                                 f2tf(Vg[(s + 3) * HD + vd]));
            *(uint4*)&Vt[vd * APITCH + s] = u;
        }
        if (tid < 64)
            maskF[tid] = mask[b * SEQ + kt * 64 + tid] ? 0.f : -CUDART_INF_F;
        __syncthreads();

        // ---- S = Q K^T ----
        float s[8][4];
        #pragma unroll
        for (int nt = 0; nt < 8; nt++)
            s[nt][0] = s[nt][1] = s[nt][2] = s[nt][3] = 0.f;
        #pragma unroll
        for (int k8 = 0; k8 < 8; k8++) {
            uint32_t bf[4][4];
            #pragma unroll
            for (int np = 0; np < 4; np++)
                ldm4(bf[np], sK + ((np * 16 + b_row) * APITCH + k8 * 8 + b_kof) * 4);
            #pragma unroll
            for (int nt = 0; nt < 8; nt++)
                mma_tf32(s[nt], aq[k8],
                         bf[nt >> 1][(nt & 1) * 2], bf[nt >> 1][(nt & 1) * 2 + 1]);
        }

        // ---- scale + mask + online softmax ----
        float mx0 = -CUDART_INF_F, mx1 = -CUDART_INF_F;
        #pragma unroll
        for (int nt = 0; nt < 8; nt++) {
            float f0 = maskF[nt * 8 + q2];
            float f1 = maskF[nt * 8 + q2 + 1];
            s[nt][0] = s[nt][0] * 0.125f + f0;
            s[nt][1] = s[nt][1] * 0.125f + f1;
            s[nt][2] = s[nt][2] * 0.125f + f0;
            s[nt][3] = s[nt][3] * 0.125f + f1;
            mx0 = fmaxf(mx0, fmaxf(s[nt][0], s[nt][1]));
            mx1 = fmaxf(mx1, fmaxf(s[nt][2], s[nt][3]));
        }
        mx0 = fmaxf(mx0, __shfl_xor_sync(0xffffffffu, mx0, 1));
        mx0 = fmaxf(mx0, __shfl_xor_sync(0xffffffffu, mx0, 2));
        mx1 = fmaxf(mx1, __shfl_xor_sync(0xffffffffu, mx1, 1));
        mx1 = fmaxf(mx1, __shfl_xor_sync(0xffffffffu, mx1, 2));

        float mn0 = fmaxf(mI0, mx0), mn1 = fmaxf(mI1, mx1);
        float mu0 = (mn0 == -CUDART_INF_F) ? 0.f : mn0;
        float mu1 = (mn1 == -CUDART_INF_F) ? 0.f : mn1;
        float al0 = __expf(mI0 - mu0), al1 = __expf(mI1 - mu1);
        float rs0 = 0.f, rs1 = 0.f;
        #pragma unroll
        for (int nt = 0; nt < 8; nt++) {
            s[nt][0] = __expf(s[nt][0] - mu0);
            s[nt][1] = __expf(s[nt][1] - mu0);
            s[nt][2] = __expf(s[nt][2] - mu1);
            s[nt][3] = __expf(s[nt][3] - mu1);
            rs0 += s[nt][0] + s[nt][1];
            rs1 += s[nt][2] + s[nt][3];
        }
        rs0 += __shfl_xor_sync(0xffffffffu, rs0, 1);
        rs0 += __shfl_xor_sync(0xffffffffu, rs0, 2);
        rs1 += __shfl_xor_sync(0xffffffffu, rs1, 1);
        rs1 += __shfl_xor_sync(0xffffffffu, rs1, 2);
        l0 = l0 * al0 + rs0; mI0 = mn0;
        l1 = l1 * al1 + rs1; mI1 = mn1;
        #pragma unroll
        for (int dt = 0; dt < 8; dt++) {
            o[dt][0] *= al0; o[dt][1] *= al0;
            o[dt][2] *= al1; o[dt][3] *= al1;
        }

        // ---- store P (tf32) into warp-private rows of QPs ----
        #pragma unroll
        for (int nt = 0; nt < 8; nt++) {
            uint2 p0 = make_uint2(f2tf(s[nt][0]), f2tf(s[nt][1]));
            uint2 p1 = make_uint2(f2tf(s[nt][2]), f2tf(s[nt][3]));
            *(uint2*)&QPs[(16 * w + r0) * APITCH + nt * 8 + q2]       = p0;
            *(uint2*)&QPs[(16 * w + r0 + 8) * APITCH + nt * 8 + q2]   = p1;
        }
        __syncwarp();

        // ---- O += P V ----
        #pragma unroll
        for (int k8 = 0; k8 < 8; k8++) {
            uint32_t pf[4], vf[4][4];
            ldm4(pf, sQP + ((16 * w + a_row) * APITCH + k8 * 8 + a_kof) * 4);
            #pragma unroll
            for (int np = 0; np < 4; np++)
                ldm4(vf[np], sV + ((np * 16 + b_row) * APITCH + k8 * 8 + b_kof) * 4);
            #pragma unroll
            for (int dt = 0; dt < 8; dt++)
                mma_tf32(o[dt], pf,
                         vf[dt >> 1][(dt & 1) * 2], vf[dt >> 1][(dt & 1) * 2 + 1]);
        }
    }

    // ---- epilogue ----
    float inv0 = 1.0f / fmaxf(l0, 1e-30f);
    float inv1 = 1.0f / fmaxf(l1, 1e-30f);
    const int h = bh & 15;
    const int row0 = s0 + 16 * w + r0;
    float* op0 = out + (size_t)(b * SEQ + row0) * HID + h * HD;
    float* op1 = out + (size_t)(b * SEQ + row0 + 8) * HID + h * HD;
    #pragma unroll
    for (int dt = 0; dt < 8; dt++) {
        int d = dt * 8 + q2;
        *(float2*)&op0[d] = make_float2(o[dt][0] * inv0, o[dt][1] * inv0);
        *(float2*)&op1[d] = make_float2(o[dt][2] * inv1, o[dt][3] * inv1);
    }
}

// ---------------------------------------------------------------------------
extern "C" void kernel_launch(void* const* d_in, const int* in_sizes, int n_in,
                              void* d_out, int out_size)
{
    const float* X    = (const float*)d_in[0];
    const int*   mask = (const int*)d_in[1];
    const float* Wq   = (const float*)d_in[2];
    const float* bq   = (const float*)d_in[3];
    const float* Wk   = (const float*)d_in[4];
    const float* bk   = (const float*)d_in[5];
    const float* Wv   = (const float*)d_in[6];
    const float* bv   = (const float*)d_in[7];
    float* out = (float*)d_out;

    cudaFuncSetAttribute(qkv_mma_kernel,
                         cudaFuncAttributeMaxDynamicSharedMemorySize, QKV_SMEM);
    qkv_mma_kernel<<<dim3(32, 8, 3), 256, QKV_SMEM>>>(X, Wq, bq, Wk, bk, Wv, bv);

    cudaFuncSetAttribute(attn_mma_kernel,
                         cudaFuncAttributeMaxDynamicSharedMemorySize, ATT_SMEM);
    attn_mma_kernel<<<dim3(SEQ / 64, BSZ * NH), 128, ATT_SMEM>>>(mask, out);
}